// round 12
// baseline (speedup 1.0000x reference)
#include <cuda_runtime.h>
#include <cuda_fp16.h>

#define BB 16
#define CC 64
#define SS 4096
#define PADR 72

__device__ __half g_Q[BB * SS * CC]; // [b][s][c] f16, pre-scaled by log2e/8
__device__ __half g_K[BB * SS * CC]; // [b][s][c] f16
__device__ __half g_V[BB * CC * SS]; // [b][c][s] f16 (transposed)

__device__ __forceinline__ unsigned pf16(float lo, float hi) {
    unsigned d; asm("cvt.rn.f16x2.f32 %0, %1, %2;" : "=r"(d) : "f"(hi), "f"(lo));
    return d;
}
__device__ __forceinline__ unsigned ex2h2(unsigned h) {
    unsigned d; asm("ex2.approx.f16x2 %0, %1;" : "=r"(d) : "r"(h)); return d;
}
__device__ __forceinline__ unsigned hadd2u(unsigned a, unsigned b) {
    unsigned d; asm("add.f16x2 %0, %1, %2;" : "=r"(d) : "r"(a), "r"(b)); return d;
}
__device__ __forceinline__ float2 h2f2(unsigned h) {
    __half2 v = *reinterpret_cast<__half2*>(&h);
    return __half22float2(v);
}
__device__ __forceinline__ void ldsm4(unsigned r[4], unsigned addr) {
    asm volatile("ldmatrix.sync.aligned.m8n8.x4.shared.b16 {%0,%1,%2,%3}, [%4];"
                 : "=r"(r[0]), "=r"(r[1]), "=r"(r[2]), "=r"(r[3]) : "r"(addr));
}
__device__ __forceinline__ void mma_f16(float c[4], const unsigned a[4],
                                        unsigned b0, unsigned b1) {
    asm volatile(
        "mma.sync.aligned.m16n8k16.row.col.f32.f16.f16.f32 "
        "{%0,%1,%2,%3}, {%4,%5,%6,%7}, {%8,%9}, {%0,%1,%2,%3};"
        : "+f"(c[0]), "+f"(c[1]), "+f"(c[2]), "+f"(c[3])
        : "r"(a[0]), "r"(a[1]), "r"(a[2]), "r"(a[3]), "r"(b0), "r"(b1));
}
__device__ __forceinline__ void mma_h16(unsigned d[2], const unsigned a[4],
                                        unsigned b0, unsigned b1) {
    asm volatile(
        "mma.sync.aligned.m16n8k16.row.col.f16.f16.f16.f16 "
        "{%0,%1}, {%2,%3,%4,%5}, {%6,%7}, {%0,%1};"
        : "+r"(d[0]), "+r"(d[1])
        : "r"(a[0]), "r"(a[1]), "r"(a[2]), "r"(a[3]), "r"(b0), "r"(b1));
}
__device__ __forceinline__ void cp16(unsigned dst, const void* src) {
    asm volatile("cp.async.cg.shared.global [%0], [%1], 16;" :: "r"(dst), "l"(src));
}
#define CP_COMMIT() asm volatile("cp.async.commit_group;")
#define CP_WAIT0()  asm volatile("cp.async.wait_group 0;")

// ---------------------------------------------------------------------------
// Kernel 1: QKV projections on tensor cores (unchanged from R11).
// ---------------------------------------------------------------------------
__global__ __launch_bounds__(128) void qkv_kernel(
    const float* __restrict__ x,
    const float* __restrict__ qw, const float* __restrict__ qb,
    const float* __restrict__ kw, const float* __restrict__ kb,
    const float* __restrict__ vw, const float* __restrict__ vb)
{
    __shared__ __half Xs[64 * PADR];
    __shared__ __half Ws[3][64 * PADR];

    const int b = blockIdx.y, s0 = blockIdx.x * 64, tid = threadIdx.x;
    const int warp = tid >> 5, lane = tid & 31;
    const int g = lane >> 2, tig = lane & 3, qb_r = warp * 16;
    const int lrow = (lane & 7) + ((lane & 16) >> 1);
    const int lcol = lane & 8;

    const float* Wp[3] = {qw, kw, vw};
    #pragma unroll
    for (int w = 0; w < 3; ++w) {
        unsigned* Wu = (unsigned*)Ws[w];
        for (int i = tid; i < 2048; i += 128) {
            int o = i >> 5, cp = i & 31;
            float2 wv = *(const float2*)&Wp[w][o * 64 + cp * 2];
            Wu[o * 36 + cp] = pf16(wv.x, wv.y);
        }
    }
    const float* xb = x + (size_t)b * CC * SS;
    for (int i = tid; i < 4096; i += 128) {
        int c = i >> 6, t = i & 63;
        Xs[t * PADR + c] = __float2half(xb[c * SS + s0 + t]);
    }
    __syncthreads();

    const unsigned XsB = (unsigned)__cvta_generic_to_shared(Xs);
    const unsigned WqB = (unsigned)__cvta_generic_to_shared(Ws[0]);
    const unsigned WkB = (unsigned)__cvta_generic_to_shared(Ws[1]);

    unsigned ax[4][4], av[4][4];
    #pragma unroll
    for (int kc = 0; kc < 4; ++kc) {
        ax[kc][0] = *(const unsigned*)&Xs[(qb_r + g)     * PADR + kc * 16 + tig * 2];
        ax[kc][1] = *(const unsigned*)&Xs[(qb_r + g + 8) * PADR + kc * 16 + tig * 2];
        ax[kc][2] = *(const unsigned*)&Xs[(qb_r + g)     * PADR + kc * 16 + 8 + tig * 2];
        ax[kc][3] = *(const unsigned*)&Xs[(qb_r + g + 8) * PADR + kc * 16 + 8 + tig * 2];
        av[kc][0] = *(const unsigned*)&Ws[2][(qb_r + g)     * PADR + kc * 16 + tig * 2];
        av[kc][1] = *(const unsigned*)&Ws[2][(qb_r + g + 8) * PADR + kc * 16 + tig * 2];
        av[kc][2] = *(const unsigned*)&Ws[2][(qb_r + g)     * PADR + kc * 16 + 8 + tig * 2];
        av[kc][3] = *(const unsigned*)&Ws[2][(qb_r + g + 8) * PADR + kc * 16 + 8 + tig * 2];
    }

    float sq[8][4], sk[8][4], sv[8][4];
    #pragma unroll
    for (int nt = 0; nt < 8; ++nt)
        #pragma unroll
        for (int j = 0; j < 4; ++j) { sq[nt][j] = 0.f; sk[nt][j] = 0.f; sv[nt][j] = 0.f; }

    #pragma unroll
    for (int kc = 0; kc < 4; ++kc)
        #pragma unroll
        for (int np = 0; np < 4; ++np) {
            unsigned off = ((np * 16 + lrow) * PADR + kc * 16 + lcol) * 2;
            unsigned r[4];
            ldsm4(r, WqB + off);
            mma_f16(sq[2*np], ax[kc], r[0], r[1]); mma_f16(sq[2*np+1], ax[kc], r[2], r[3]);
            ldsm4(r, WkB + off);
            mma_f16(sk[2*np], ax[kc], r[0], r[1]); mma_f16(sk[2*np+1], ax[kc], r[2], r[3]);
            ldsm4(r, XsB + off);
            mma_f16(sv[2*np], av[kc], r[0], r[1]); mma_f16(sv[2*np+1], av[kc], r[2], r[3]);
        }

    const float sc = 0.125f * 1.4426950408889634f;
    const int r0 = s0 + qb_r + g;
    float bv0 = __ldg(&vb[qb_r + g]), bv8 = __ldg(&vb[qb_r + g + 8]);
    #pragma unroll
    for (int nt = 0; nt < 8; ++nt) {
        int c = nt * 8 + tig * 2;
        float bq0 = __ldg(&qb[c]), bq1 = __ldg(&qb[c+1]);
        float bk0 = __ldg(&kb[c]), bk1 = __ldg(&kb[c+1]);
        *(unsigned*)&g_Q[((size_t)b*SS + r0)     * CC + c] = pf16((sq[nt][0]+bq0)*sc, (sq[nt][1]+bq1)*sc);
        *(unsigned*)&g_Q[((size_t)b*SS + r0 + 8) * CC + c] = pf16((sq[nt][2]+bq0)*sc, (sq[nt][3]+bq1)*sc);
        *(unsigned*)&g_K[((size_t)b*SS + r0)     * CC + c] = pf16(sk[nt][0]+bk0, sk[nt][1]+bk1);
        *(unsigned*)&g_K[((size_t)b*SS + r0 + 8) * CC + c] = pf16(sk[nt][2]+bk0, sk[nt][3]+bk1);
        int tok = s0 + nt * 8 + tig * 2;
        *(unsigned*)&g_V[((size_t)b*CC + qb_r + g)     * SS + tok] = pf16(sv[nt][0]+bv0, sv[nt][1]+bv0);
        *(unsigned*)&g_V[((size_t)b*CC + qb_r + g + 8) * SS + tok] = pf16(sv[nt][2]+bv8, sv[nt][3]+bv8);
    }
}

// ---------------------------------------------------------------------------
// Kernel 2: flash attention. M=128/CTA, 256 threads, 2 CTAs/SM.
// QK f16-accum; ex2 interleaved into the PV kc-loop (no phase bubble);
// row sums on ALU (add.f16x2 fold) instead of a tensor-pipe ones-MMA.
// ---------------------------------------------------------------------------
#define TILEB 9216u
#define ATTN_SMEM_BYTES 55296

__global__ __launch_bounds__(256, 2) void attn_kernel(
    const float* __restrict__ ow, const float* __restrict__ ob,
    float* __restrict__ y)
{
    extern __shared__ __half smb[];
    __half* Qs = smb;
    const unsigned SB  = (unsigned)__cvta_generic_to_shared(smb);
    const unsigned KB0 = SB + 18432u;
    const unsigned VB0 = SB + 18432u + 2u * TILEB;

    const int b  = blockIdx.y;
    const int q0 = blockIdx.x * 128;
    const int tid  = threadIdx.x;
    const int warp = tid >> 5;
    const int lane = tid & 31;
    const int g   = lane >> 2;
    const int tig = lane & 3;
    const int qb  = warp * 16;

    const __half* Qg = g_Q + ((size_t)b * SS + q0) * CC;
    const __half* Kg = g_K + (size_t)b * SS * CC;
    const __half* Vg = g_V + (size_t)b * CC * SS;

    {
        uint4* Qs4 = (uint4*)Qs;
        const uint4* Qg4 = (const uint4*)Qg;
        for (int i = tid; i < 1024; i += 256) {
            int row = i >> 3, ch = i & 7;
            Qs4[row * 9 + ch] = Qg4[row * 8 + ch];
        }
    }
    __syncthreads();

    unsigned qa[4][4];
    #pragma unroll
    for (int kc = 0; kc < 4; ++kc) {
        qa[kc][0] = *(const unsigned*)&Qs[(qb + g)     * PADR + kc * 16 + tig * 2];
        qa[kc][1] = *(const unsigned*)&Qs[(qb + g + 8) * PADR + kc * 16 + tig * 2];
        qa[kc][2] = *(const unsigned*)&Qs[(qb + g)     * PADR + kc * 16 + 8 + tig * 2];
        qa[kc][3] = *(const unsigned*)&Qs[(qb + g + 8) * PADR + kc * 16 + 8 + tig * 2];
    }
    __syncthreads();

    {
        unsigned* OWu = (unsigned*)Qs;
        for (int i = tid; i < 2048; i += 256) {
            int o = i >> 5, cp = i & 31;
            float2 wv = *(const float2*)&ow[o * 64 + cp * 2];
            OWu[o * 36 + cp] = pf16(wv.x, wv.y);
        }
    }

    const int lrow = (lane & 7) + ((lane & 16) >> 1);
    const int lcol = lane & 8;

    float l0 = 0.f, l8 = 0.f;
    float o[8][4];
    #pragma unroll
    for (int nt = 0; nt < 8; ++nt)
        #pragma unroll
        for (int j = 0; j < 4; ++j) o[nt][j] = 0.f;

    #pragma unroll
    for (int j = 0; j < 2; ++j) {
        int i = tid + j * 256, row = i >> 3, ch = i & 7;
        cp16(KB0 + (row * 9 + ch) * 16, Kg + (size_t)row * CC + ch * 8);
        cp16(VB0 + (row * 9 + ch) * 16, Vg + (size_t)row * SS + ch * 8);
    }
    CP_COMMIT();

    for (int kblk = 0; kblk < SS / 64; ++kblk) {
        const unsigned bo = (unsigned)(kblk & 1) * TILEB;
        const unsigned KsB = KB0 + bo;
        const unsigned VsB = VB0 + bo;

        CP_WAIT0();
        __syncthreads();

        if (kblk < SS / 64 - 1) {
            const int k1 = (kblk + 1) * 64;
            const unsigned bn = (unsigned)((kblk + 1) & 1) * TILEB;
            #pragma unroll
            for (int j = 0; j < 2; ++j) {
                int i = tid + j * 256, row = i >> 3, ch = i & 7;
                cp16(KB0 + bn + (row * 9 + ch) * 16,
                     Kg + (size_t)(k1 + row) * CC + ch * 8);
                cp16(VB0 + bn + (row * 9 + ch) * 16,
                     Vg + (size_t)row * SS + k1 + ch * 8);
            }
            CP_COMMIT();
        }

        // ---- S = Q K^T (f16 accum; D-frag = packed layout) ----
        unsigned s2[8][2];
        #pragma unroll
        for (int nt = 0; nt < 8; ++nt) { s2[nt][0] = 0u; s2[nt][1] = 0u; }

        #pragma unroll
        for (int kc = 0; kc < 4; ++kc)
            #pragma unroll
            for (int np = 0; np < 4; ++np) {
                unsigned r[4];
                ldsm4(r, KsB + ((np * 16 + lrow) * PADR + kc * 16 + lcol) * 2);
                mma_h16(s2[2*np],     qa[kc], r[0], r[1]);
                mma_h16(s2[2*np + 1], qa[kc], r[2], r[3]);
            }

        // ---- PV with just-in-time P = 2^S and ALU row-sum fold ----
        #pragma unroll
        for (int kc = 0; kc < 4; ++kc) {
            unsigned pa[4];
            pa[0] = ex2h2(s2[2*kc][0]);
            pa[1] = ex2h2(s2[2*kc][1]);
            pa[2] = ex2h2(s2[2*kc + 1][0]);
            pa[3] = ex2h2(s2[2*kc + 1][1]);

            // row sums on ALU (tensor pipe freed): rows g and g+8
            float2 fg = h2f2(hadd2u(pa[0], pa[2]));
            float2 f8 = h2f2(hadd2u(pa[1], pa[3]));
            l0 += fg.x + fg.y;
            l8 += f8.x + f8.y;

            #pragma unroll
            for (int np = 0; np < 4; ++np) {
                unsigned r[4];
                ldsm4(r, VsB + ((np * 16 + lrow) * PADR + kc * 16 + lcol) * 2);
                mma_f16(o[2*np],     pa, r[0], r[1]);
                mma_f16(o[2*np + 1], pa, r[2], r[3]);
            }
        }
    }

    // reduce per-lane partial row sums across the 4-lane groups
    #pragma unroll
    for (int off = 1; off <= 2; off <<= 1) {
        l0 += __shfl_xor_sync(0xffffffffu, l0, off);
        l8 += __shfl_xor_sync(0xffffffffu, l8, off);
    }

    // ---- fused epilogue: Y = (O/l) @ OW^T + ob ----
    float inv0 = 1.f / l0, inv8 = 1.f / l8;
    float yacc[8][4];
    #pragma unroll
    for (int nt = 0; nt < 8; ++nt)
        #pragma unroll
        for (int j = 0; j < 4; ++j) yacc[nt][j] = 0.f;

    #pragma unroll
    for (int kc = 0; kc < 4; ++kc) {
        unsigned pa[4];
        pa[0] = pf16(o[2*kc][0] * inv0,     o[2*kc][1] * inv0);
        pa[1] = pf16(o[2*kc][2] * inv8,     o[2*kc][3] * inv8);
        pa[2] = pf16(o[2*kc + 1][0] * inv0, o[2*kc + 1][1] * inv0);
        pa[3] = pf16(o[2*kc + 1][2] * inv8, o[2*kc + 1][3] * inv8);
        #pragma unroll
        for (int np = 0; np < 4; ++np) {
            unsigned r[4];
            ldsm4(r, SB + ((np * 16 + lrow) * PADR + kc * 16 + lcol) * 2);
            mma_f16(yacc[2*np],     pa, r[0], r[1]);
            mma_f16(yacc[2*np + 1], pa, r[2], r[3]);
        }
    }

    const int t0 = q0 + qb + g;
    #pragma unroll
    for (int nt = 0; nt < 8; ++nt) {
        int c = nt * 8 + tig * 2;
        float b0 = __ldg(&ob[c]), b1 = __ldg(&ob[c + 1]);
        y[((size_t)b * CC + c)     * SS + t0]     = yacc[nt][0] + b0;
        y[((size_t)b * CC + c + 1) * SS + t0]     = yacc[nt][1] + b1;
        y[((size_t)b * CC + c)     * SS + t0 + 8] = yacc[nt][2] + b0;
        y[((size_t)b * CC + c + 1) * SS + t0 + 8] = yacc[nt][3] + b1;
    }
}

// ---------------------------------------------------------------------------
extern "C" void kernel_launch(void* const* d_in, const int* in_sizes, int n_in,
                              void* d_out, int out_size)
{
    const float* x  = (const float*)d_in[0];
    const float* qw = (const float*)d_in[1];
    const float* qb = (const float*)d_in[2];
    const float* kw = (const float*)d_in[3];
    const float* kb = (const float*)d_in[4];
    const float* vw = (const float*)d_in[5];
    const float* vb = (const float*)d_in[6];
    const float* ow = (const float*)d_in[7];
    const float* ob = (const float*)d_in[8];
    float* y = (float*)d_out;

    cudaFuncSetAttribute(attn_kernel,
                         cudaFuncAttributeMaxDynamicSharedMemorySize,
                         ATTN_SMEM_BYTES);

    qkv_kernel <<<dim3(SS / 64, BB), 128>>>(x, qw, qb, kw, kb, vw, vb);
    attn_kernel<<<dim3(SS / 128, BB), 256, ATTN_SMEM_BYTES>>>(ow, ob, y);
}

// round 13
// speedup vs baseline: 1.0278x; 1.0278x over previous
#include <cuda_runtime.h>
#include <cuda_fp16.h>

#define BB 16
#define CC 64
#define SS 4096
#define PADR 72

__device__ __half g_Q[BB * SS * CC]; // [b][s][c] f16, pre-scaled by log2e/8
__device__ __half g_K[BB * SS * CC]; // [b][s][c] f16
__device__ __half g_V[BB * CC * SS]; // [b][c][s] f16 (transposed)

__device__ __forceinline__ unsigned pf16(float lo, float hi) {
    unsigned d; asm("cvt.rn.f16x2.f32 %0, %1, %2;" : "=r"(d) : "f"(hi), "f"(lo));
    return d;
}
__device__ __forceinline__ unsigned ex2h2(unsigned h) {
    unsigned d; asm("ex2.approx.f16x2 %0, %1;" : "=r"(d) : "r"(h)); return d;
}
__device__ __forceinline__ unsigned hadd2u(unsigned a, unsigned b) {
    unsigned d; asm("add.f16x2 %0, %1, %2;" : "=r"(d) : "r"(a), "r"(b)); return d;
}
__device__ __forceinline__ float2 h2f2(unsigned h) {
    __half2 v = *reinterpret_cast<__half2*>(&h);
    return __half22float2(v);
}
__device__ __forceinline__ void ldsm4(unsigned r[4], unsigned addr) {
    asm volatile("ldmatrix.sync.aligned.m8n8.x4.shared.b16 {%0,%1,%2,%3}, [%4];"
                 : "=r"(r[0]), "=r"(r[1]), "=r"(r[2]), "=r"(r[3]) : "r"(addr));
}
__device__ __forceinline__ void mma_f16(float c[4], const unsigned a[4],
                                        unsigned b0, unsigned b1) {
    asm volatile(
        "mma.sync.aligned.m16n8k16.row.col.f32.f16.f16.f32 "
        "{%0,%1,%2,%3}, {%4,%5,%6,%7}, {%8,%9}, {%0,%1,%2,%3};"
        : "+f"(c[0]), "+f"(c[1]), "+f"(c[2]), "+f"(c[3])
        : "r"(a[0]), "r"(a[1]), "r"(a[2]), "r"(a[3]), "r"(b0), "r"(b1));
}
__device__ __forceinline__ void mma_h16(unsigned d[2], const unsigned a[4],
                                        unsigned b0, unsigned b1) {
    asm volatile(
        "mma.sync.aligned.m16n8k16.row.col.f16.f16.f16.f16 "
        "{%0,%1}, {%2,%3,%4,%5}, {%6,%7}, {%0,%1};"
        : "+r"(d[0]), "+r"(d[1])
        : "r"(a[0]), "r"(a[1]), "r"(a[2]), "r"(a[3]), "r"(b0), "r"(b1));
}
__device__ __forceinline__ void cp16(unsigned dst, const void* src) {
    asm volatile("cp.async.cg.shared.global [%0], [%1], 16;" :: "r"(dst), "l"(src));
}
#define CP_COMMIT() asm volatile("cp.async.commit_group;")
#define CP_WAIT0()  asm volatile("cp.async.wait_group 0;")

// ---------------------------------------------------------------------------
// Kernel 1: QKV projections on tensor cores (unchanged).
// ---------------------------------------------------------------------------
__global__ __launch_bounds__(128) void qkv_kernel(
    const float* __restrict__ x,
    const float* __restrict__ qw, const float* __restrict__ qb,
    const float* __restrict__ kw, const float* __restrict__ kb,
    const float* __restrict__ vw, const float* __restrict__ vb)
{
    __shared__ __half Xs[64 * PADR];
    __shared__ __half Ws[3][64 * PADR];

    const int b = blockIdx.y, s0 = blockIdx.x * 64, tid = threadIdx.x;
    const int warp = tid >> 5, lane = tid & 31;
    const int g = lane >> 2, tig = lane & 3, qb_r = warp * 16;
    const int lrow = (lane & 7) + ((lane & 16) >> 1);
    const int lcol = lane & 8;

    const float* Wp[3] = {qw, kw, vw};
    #pragma unroll
    for (int w = 0; w < 3; ++w) {
        unsigned* Wu = (unsigned*)Ws[w];
        for (int i = tid; i < 2048; i += 128) {
            int o = i >> 5, cp = i & 31;
            float2 wv = *(const float2*)&Wp[w][o * 64 + cp * 2];
            Wu[o * 36 + cp] = pf16(wv.x, wv.y);
        }
    }
    const float* xb = x + (size_t)b * CC * SS;
    for (int i = tid; i < 4096; i += 128) {
        int c = i >> 6, t = i & 63;
        Xs[t * PADR + c] = __float2half(xb[c * SS + s0 + t]);
    }
    __syncthreads();

    const unsigned XsB = (unsigned)__cvta_generic_to_shared(Xs);
    const unsigned WqB = (unsigned)__cvta_generic_to_shared(Ws[0]);
    const unsigned WkB = (unsigned)__cvta_generic_to_shared(Ws[1]);

    unsigned ax[4][4], av[4][4];
    #pragma unroll
    for (int kc = 0; kc < 4; ++kc) {
        ax[kc][0] = *(const unsigned*)&Xs[(qb_r + g)     * PADR + kc * 16 + tig * 2];
        ax[kc][1] = *(const unsigned*)&Xs[(qb_r + g + 8) * PADR + kc * 16 + tig * 2];
        ax[kc][2] = *(const unsigned*)&Xs[(qb_r + g)     * PADR + kc * 16 + 8 + tig * 2];
        ax[kc][3] = *(const unsigned*)&Xs[(qb_r + g + 8) * PADR + kc * 16 + 8 + tig * 2];
        av[kc][0] = *(const unsigned*)&Ws[2][(qb_r + g)     * PADR + kc * 16 + tig * 2];
        av[kc][1] = *(const unsigned*)&Ws[2][(qb_r + g + 8) * PADR + kc * 16 + tig * 2];
        av[kc][2] = *(const unsigned*)&Ws[2][(qb_r + g)     * PADR + kc * 16 + 8 + tig * 2];
        av[kc][3] = *(const unsigned*)&Ws[2][(qb_r + g + 8) * PADR + kc * 16 + 8 + tig * 2];
    }

    float sq[8][4], sk[8][4], sv[8][4];
    #pragma unroll
    for (int nt = 0; nt < 8; ++nt)
        #pragma unroll
        for (int j = 0; j < 4; ++j) { sq[nt][j] = 0.f; sk[nt][j] = 0.f; sv[nt][j] = 0.f; }

    #pragma unroll
    for (int kc = 0; kc < 4; ++kc)
        #pragma unroll
        for (int np = 0; np < 4; ++np) {
            unsigned off = ((np * 16 + lrow) * PADR + kc * 16 + lcol) * 2;
            unsigned r[4];
            ldsm4(r, WqB + off);
            mma_f16(sq[2*np], ax[kc], r[0], r[1]); mma_f16(sq[2*np+1], ax[kc], r[2], r[3]);
            ldsm4(r, WkB + off);
            mma_f16(sk[2*np], ax[kc], r[0], r[1]); mma_f16(sk[2*np+1], ax[kc], r[2], r[3]);
            ldsm4(r, XsB + off);
            mma_f16(sv[2*np], av[kc], r[0], r[1]); mma_f16(sv[2*np+1], av[kc], r[2], r[3]);
        }

    const float sc = 0.125f * 1.4426950408889634f;
    const int r0 = s0 + qb_r + g;
    float bv0 = __ldg(&vb[qb_r + g]), bv8 = __ldg(&vb[qb_r + g + 8]);
    #pragma unroll
    for (int nt = 0; nt < 8; ++nt) {
        int c = nt * 8 + tig * 2;
        float bq0 = __ldg(&qb[c]), bq1 = __ldg(&qb[c+1]);
        float bk0 = __ldg(&kb[c]), bk1 = __ldg(&kb[c+1]);
        *(unsigned*)&g_Q[((size_t)b*SS + r0)     * CC + c] = pf16((sq[nt][0]+bq0)*sc, (sq[nt][1]+bq1)*sc);
        *(unsigned*)&g_Q[((size_t)b*SS + r0 + 8) * CC + c] = pf16((sq[nt][2]+bq0)*sc, (sq[nt][3]+bq1)*sc);
        *(unsigned*)&g_K[((size_t)b*SS + r0)     * CC + c] = pf16(sk[nt][0]+bk0, sk[nt][1]+bk1);
        *(unsigned*)&g_K[((size_t)b*SS + r0 + 8) * CC + c] = pf16(sk[nt][2]+bk0, sk[nt][3]+bk1);
        int tok = s0 + nt * 8 + tig * 2;
        *(unsigned*)&g_V[((size_t)b*CC + qb_r + g)     * SS + tok] = pf16(sv[nt][0]+bv0, sv[nt][1]+bv0);
        *(unsigned*)&g_V[((size_t)b*CC + qb_r + g + 8) * SS + tok] = pf16(sv[nt][2]+bv8, sv[nt][3]+bv8);
    }
}

// ---------------------------------------------------------------------------
// Kernel 2: flash attention. 128 threads (4 warps), M=128/CTA, 32 rows/warp:
// each ldsm4 B-fragment feeds 4 MMAs (2 m-tiles) -> smem bytes/MMA halved,
// breaking the LDSM/tensor co-saturation. 3 CTAs/SM.
// ---------------------------------------------------------------------------
#define TILEB 9216u
#define ATTN_SMEM_BYTES 55296

__global__ __launch_bounds__(128, 3) void attn_kernel(
    const float* __restrict__ ow, const float* __restrict__ ob,
    float* __restrict__ y)
{
    extern __shared__ __half smb[];
    __half* Qs = smb;
    const unsigned SB  = (unsigned)__cvta_generic_to_shared(smb);
    const unsigned KB0 = SB + 18432u;
    const unsigned VB0 = SB + 18432u + 2u * TILEB;

    const int b  = blockIdx.y;
    const int q0 = blockIdx.x * 128;
    const int tid  = threadIdx.x;
    const int warp = tid >> 5;
    const int lane = tid & 31;
    const int g   = lane >> 2;
    const int tig = lane & 3;
    const int qb  = warp * 32;          // 32 rows per warp (2 m-tiles)

    const __half* Qg = g_Q + ((size_t)b * SS + q0) * CC;
    const __half* Kg = g_K + (size_t)b * SS * CC;
    const __half* Vg = g_V + (size_t)b * CC * SS;

    {
        uint4* Qs4 = (uint4*)Qs;
        const uint4* Qg4 = (const uint4*)Qg;
        for (int i = tid; i < 1024; i += 128) {
            int row = i >> 3, ch = i & 7;
            Qs4[row * 9 + ch] = Qg4[row * 8 + ch];
        }
    }
    __syncthreads();

    unsigned qa[2][4][4];
    #pragma unroll
    for (int m = 0; m < 2; ++m) {
        const int rb = qb + m * 16;
        #pragma unroll
        for (int kc = 0; kc < 4; ++kc) {
            qa[m][kc][0] = *(const unsigned*)&Qs[(rb + g)     * PADR + kc * 16 + tig * 2];
            qa[m][kc][1] = *(const unsigned*)&Qs[(rb + g + 8) * PADR + kc * 16 + tig * 2];
            qa[m][kc][2] = *(const unsigned*)&Qs[(rb + g)     * PADR + kc * 16 + 8 + tig * 2];
            qa[m][kc][3] = *(const unsigned*)&Qs[(rb + g + 8) * PADR + kc * 16 + 8 + tig * 2];
        }
    }
    __syncthreads();

    {   // OW tile (fp32 -> f16) into rows 0..63 of Q region
        unsigned* OWu = (unsigned*)Qs;
        for (int i = tid; i < 2048; i += 128) {
            int o = i >> 5, cp = i & 31;
            float2 wv = *(const float2*)&ow[o * 64 + cp * 2];
            OWu[o * 36 + cp] = pf16(wv.x, wv.y);
        }
    }

    const int lrow = (lane & 7) + ((lane & 16) >> 1);
    const int lcol = lane & 8;

    float l[2][2] = {{0.f, 0.f}, {0.f, 0.f}};
    float o[2][8][4];
    #pragma unroll
    for (int m = 0; m < 2; ++m)
        #pragma unroll
        for (int nt = 0; nt < 8; ++nt)
            #pragma unroll
            for (int j = 0; j < 4; ++j) o[m][nt][j] = 0.f;

    #pragma unroll
    for (int j = 0; j < 4; ++j) {
        int i = tid + j * 128, row = i >> 3, ch = i & 7;
        cp16(KB0 + (row * 9 + ch) * 16, Kg + (size_t)row * CC + ch * 8);
        cp16(VB0 + (row * 9 + ch) * 16, Vg + (size_t)row * SS + ch * 8);
    }
    CP_COMMIT();

    for (int kblk = 0; kblk < SS / 64; ++kblk) {
        const unsigned bo = (unsigned)(kblk & 1) * TILEB;
        const unsigned KsB = KB0 + bo;
        const unsigned VsB = VB0 + bo;

        CP_WAIT0();
        __syncthreads();

        if (kblk < SS / 64 - 1) {
            const int k1 = (kblk + 1) * 64;
            const unsigned bn = (unsigned)((kblk + 1) & 1) * TILEB;
            #pragma unroll
            for (int j = 0; j < 4; ++j) {
                int i = tid + j * 128, row = i >> 3, ch = i & 7;
                cp16(KB0 + bn + (row * 9 + ch) * 16,
                     Kg + (size_t)(k1 + row) * CC + ch * 8);
                cp16(VB0 + bn + (row * 9 + ch) * 16,
                     Vg + (size_t)row * SS + k1 + ch * 8);
            }
            CP_COMMIT();
        }

        // ---- S = Q K^T (f16 accum). One ldsm4 feeds both m-tiles. ----
        unsigned s2[2][8][2];
        #pragma unroll
        for (int m = 0; m < 2; ++m)
            #pragma unroll
            for (int nt = 0; nt < 8; ++nt) { s2[m][nt][0] = 0u; s2[m][nt][1] = 0u; }

        #pragma unroll
        for (int kc = 0; kc < 4; ++kc)
            #pragma unroll
            for (int np = 0; np < 4; ++np) {
                unsigned r[4];
                ldsm4(r, KsB + ((np * 16 + lrow) * PADR + kc * 16 + lcol) * 2);
                #pragma unroll
                for (int m = 0; m < 2; ++m) {
                    mma_h16(s2[m][2*np],     qa[m][kc], r[0], r[1]);
                    mma_h16(s2[m][2*np + 1], qa[m][kc], r[2], r[3]);
                }
            }

        // ---- PV with just-in-time P = 2^S; ALU row-sum fold ----
        #pragma unroll
        for (int kc = 0; kc < 4; ++kc) {
            unsigned pa[2][4];
            #pragma unroll
            for (int m = 0; m < 2; ++m) {
                pa[m][0] = ex2h2(s2[m][2*kc][0]);
                pa[m][1] = ex2h2(s2[m][2*kc][1]);
                pa[m][2] = ex2h2(s2[m][2*kc + 1][0]);
                pa[m][3] = ex2h2(s2[m][2*kc + 1][1]);
                float2 fg = h2f2(hadd2u(pa[m][0], pa[m][2]));
                float2 f8 = h2f2(hadd2u(pa[m][1], pa[m][3]));
                l[m][0] += fg.x + fg.y;
                l[m][1] += f8.x + f8.y;
            }
            #pragma unroll
            for (int np = 0; np < 4; ++np) {
                unsigned r[4];
                ldsm4(r, VsB + ((np * 16 + lrow) * PADR + kc * 16 + lcol) * 2);
                #pragma unroll
                for (int m = 0; m < 2; ++m) {
                    mma_f16(o[m][2*np],     pa[m], r[0], r[1]);
                    mma_f16(o[m][2*np + 1], pa[m], r[2], r[3]);
                }
            }
        }
    }

    // reduce per-lane partial row sums across 4-lane groups
    #pragma unroll
    for (int m = 0; m < 2; ++m)
        #pragma unroll
        for (int off = 1; off <= 2; off <<= 1) {
            l[m][0] += __shfl_xor_sync(0xffffffffu, l[m][0], off);
            l[m][1] += __shfl_xor_sync(0xffffffffu, l[m][1], off);
        }

    // ---- fused epilogue per m-tile: Y = (O/l) @ OW^T + ob ----
    #pragma unroll
    for (int m = 0; m < 2; ++m) {
        float inv0 = 1.f / l[m][0], inv8 = 1.f / l[m][1];
        float yacc[8][4];
        #pragma unroll
        for (int nt = 0; nt < 8; ++nt)
            #pragma unroll
            for (int j = 0; j < 4; ++j) yacc[nt][j] = 0.f;

        #pragma unroll
        for (int kc = 0; kc < 4; ++kc) {
            unsigned pa[4];
            pa[0] = pf16(o[m][2*kc][0] * inv0,     o[m][2*kc][1] * inv0);
            pa[1] = pf16(o[m][2*kc][2] * inv8,     o[m][2*kc][3] * inv8);
            pa[2] = pf16(o[m][2*kc + 1][0] * inv0, o[m][2*kc + 1][1] * inv0);
            pa[3] = pf16(o[m][2*kc + 1][2] * inv8, o[m][2*kc + 1][3] * inv8);
            #pragma unroll
            for (int np = 0; np < 4; ++np) {
                unsigned r[4];
                ldsm4(r, SB + ((np * 16 + lrow) * PADR + kc * 16 + lcol) * 2);
                mma_f16(yacc[2*np],     pa, r[0], r[1]);
                mma_f16(yacc[2*np + 1], pa, r[2], r[3]);
            }
        }

        const int t0 = q0 + qb + m * 16 + g;
        #pragma unroll
        for (int nt = 0; nt < 8; ++nt) {
            int c = nt * 8 + tig * 2;
            float b0 = __ldg(&ob[c]), b1 = __ldg(&ob[c + 1]);
            y[((size_t)b * CC + c)     * SS + t0]     = yacc[nt][0] + b0;
            y[((size_t)b * CC + c + 1) * SS + t0]     = yacc[nt][1] + b1;
            y[((size_t)b * CC + c)     * SS + t0 + 8] = yacc[nt][2] + b0;
            y[((size_t)b * CC + c + 1) * SS + t0 + 8] = yacc[nt][3] + b1;
        }
    }
}

// ---------------------------------------------------------------------------
extern "C" void kernel_launch(void* const* d_in, const int* in_sizes, int n_in,
                              void* d_out, int out_size)
{
    const float* x  = (const float*)d_in[0];
    const float* qw = (const float*)d_in[1];
    const float* qb = (const float*)d_in[2];
    const float* kw = (const float*)d_in[3];
    const float* kb = (const float*)d_in[4];
    const float* vw = (const float*)d_in[5];
    const float* vb = (const float*)d_in[6];
    const float* ow = (const float*)d_in[7];
    const float* ob = (const float*)d_in[8];
    float* y = (float*)d_out;

    cudaFuncSetAttribute(attn_kernel,
                         cudaFuncAttributeMaxDynamicSharedMemorySize,
                         ATTN_SMEM_BYTES);

    qkv_kernel <<<dim3(SS / 64, BB), 128>>>(x, qw, qb, kw, kb, vw, vb);
    attn_kernel<<<dim3(SS / 128, BB), 128, ATTN_SMEM_BYTES>>>(ow, ob, y);
}